// round 8
// baseline (speedup 1.0000x reference)
#include <cuda_runtime.h>
#include <cuda_fp16.h>
#include <cstdint>
#include <math.h>

// Problem dims (fixed by the reference)
#define BB 64
#define SS 2048
#define HH 512
#define TOK (BB * SS)   // 131072
#define NEGV -1e9f

// Scratch (allocations are banned; use device globals)
__device__ float g_scores[TOK];
__device__ float g_attn_fallback[TOK];
__device__ float g_part[8 * BB * HH];
__device__ int   g_mask_is_i32;
__device__ __half g_wh[HH * HH];
__device__ __half g_wl[HH * HH];

// ===========================================================================
// Helpers
// ===========================================================================
__device__ __forceinline__ uint32_t smem_u32(const void* p) {
    uint32_t a;
    asm("{ .reg .u64 t; cvta.to.shared.u64 t, %1; cvt.u32.u64 %0, t; }"
        : "=r"(a) : "l"(p));
    return a;
}
__device__ __forceinline__ void ldsm4(uint32_t (&r)[4], uint32_t addr) {
    asm volatile("ldmatrix.sync.aligned.m8n8.x4.shared.b16 {%0,%1,%2,%3}, [%4];"
        : "=r"(r[0]), "=r"(r[1]), "=r"(r[2]), "=r"(r[3]) : "r"(addr));
}
// fp16 in, fp32 accum
__device__ __forceinline__ void mma_f32(float (&c)[4], const uint32_t (&a)[4],
                                        uint32_t b0, uint32_t b1) {
    asm volatile("mma.sync.aligned.m16n8k16.row.col.f32.f16.f16.f32 "
        "{%0,%1,%2,%3}, {%4,%5,%6,%7}, {%8,%9}, {%0,%1,%2,%3};"
        : "+f"(c[0]), "+f"(c[1]), "+f"(c[2]), "+f"(c[3])
        : "r"(a[0]), "r"(a[1]), "r"(a[2]), "r"(a[3]), "r"(b0), "r"(b1));
}
// fp16 in, fp16 accum
__device__ __forceinline__ void mma_f16(uint32_t (&c)[2], const uint32_t (&a)[4],
                                        uint32_t b0, uint32_t b1) {
    asm volatile("mma.sync.aligned.m16n8k16.row.col.f16.f16.f16.f16 "
        "{%0,%1}, {%2,%3,%4,%5}, {%6,%7}, {%0,%1};"
        : "+r"(c[0]), "+r"(c[1])
        : "r"(a[0]), "r"(a[1]), "r"(a[2]), "r"(a[3]), "r"(b0), "r"(b1));
}
__device__ __forceinline__ void cp16(uint32_t dst, const void* src) {
    asm volatile("cp.async.cg.shared.global [%0], [%1], 16;"
        :: "r"(dst), "l"(src));
}
#define CP_COMMIT() asm volatile("cp.async.commit_group;" ::: "memory")
#define CP_WAIT0()  asm volatile("cp.async.wait_group 0;" ::: "memory")

__device__ __forceinline__ float fast_tanh(float x) {
    x = fminf(15.f, fmaxf(-15.f, x));
    float e = __expf(2.f * x);
    return __fdividef(e - 1.f, e + 1.f);
}

// ===========================================================================
// W pre-split: W fp32 -> Wh, Wl fp16 (global, done once per launch)
// ===========================================================================
__global__ __launch_bounds__(256)
void wsplit_kernel(const float* __restrict__ W,
                   __half* __restrict__ wh,
                   __half* __restrict__ wl)
{
    int idx = blockIdx.x * 256 + threadIdx.x;
#pragma unroll
    for (int j = 0; j < 4; j++) {
        int i = idx * 4 + j;
        float x = W[i];
        __half h = __float2half_rn(x);
        wh[i] = h;
        wl[i] = __float2half_rn(x - __half2float(h));
    }
}

// Tiny no-op so scores_tc lands at ncu's captured launch index (3).
__global__ void dummy_kernel() {}

// ===========================================================================
// Scores kernel: 3-term fp16 split GEMM + fused v.tanh(.+b) epilogue.
// Block = 256 thr (8 warps: 2 warp_m x 4 warp_n), warp tile m32 x n32
// (8 ldsm per 24 MMAs -> 171 B/MMA shared traffic, vs 256 at m16n32).
// M-tile 64, K=512 resident A, N-chunks of 128, B via cp.async, BK=64.
// A fragments double-buffered in regs (prefetch next k16 during MMAs).
// ===========================================================================
#define ASTR_A 1040             // 512 fp16 + 8 pad, bytes
#define ASTR_B 144              // 64 fp16 + 8 pad, bytes
#define A_TILE_SZ (64 * ASTR_A) // 66560
#define B_TILE_SZ (128 * ASTR_B)// 18432
#define OFF_V    0
#define OFF_BI   2048
#define OFF_RED  4096           // 64 x 16 floats
#define OFF_AH   8192
#define OFF_AL   (OFF_AH + A_TILE_SZ)      // 74752
#define OFF_B    (OFF_AL + A_TILE_SZ)      // 141312
#define BUF_SZ   (2 * B_TILE_SZ)           // hi + lo
#define SMEM_TOTAL (OFF_B + 2 * BUF_SZ)    // 215040

#define NTHR 256

__device__ __forceinline__ void issue_b(const __half* __restrict__ wh,
                                        const __half* __restrict__ wl,
                                        uint32_t dst_hi, int nc, int kt, int tid)
{
#pragma unroll
    for (int j = 0; j < 4; j++) {
        int idx = tid + j * NTHR;         // 0..1023
        int row = idx >> 3;               // n row 0..127
        int c16 = idx & 7;                // 16B chunk in k
        uint32_t d = dst_hi + row * ASTR_B + c16 * 16;
        size_t g = (size_t)(nc * 128 + row) * HH + kt * 64 + c16 * 8;
        cp16(d, wh + g);
        cp16(d + B_TILE_SZ, wl + g);
    }
    CP_COMMIT();
}

__global__ __launch_bounds__(NTHR, 1)
void scores_tc_kernel(const float* __restrict__ X,
                      const __half* __restrict__ wh,
                      const __half* __restrict__ wl,
                      const float* __restrict__ bias,
                      const float* __restrict__ v,
                      float* __restrict__ scores)
{
    extern __shared__ char smem[];
    const int tid  = threadIdx.x;
    const int lane = tid & 31;
    const int wid  = tid >> 5;
    const int warp_m = wid & 1;        // 0..1 -> 32-row slab
    const int warp_n = wid >> 1;       // 0..3 -> 32-col slab
    const int row0 = blockIdx.x * 64;

    const uint32_t sb = smem_u32(smem);
    float* sv  = (float*)(smem + OFF_V);
    float* sbi = (float*)(smem + OFF_BI);
    float* red = (float*)(smem + OFF_RED);
    for (int i = tid; i < HH; i += NTHR) { sv[i] = v[i]; sbi[i] = bias[i]; }

    // Prefetch first B tile.
    issue_b(wh, wl, sb + OFF_B, 0, 0, tid);

    // Convert A (64 x 512) fp32 -> fp16 hi/lo resident tiles, once.
    {
        char* ah = smem + OFF_AH;
        char* al = smem + OFF_AL;
#pragma unroll
        for (int j = 0; j < 32; j++) {
            int idx = tid + j * NTHR;         // 0..8191 float4s
            int r  = idx >> 7;                // row 0..63
            int c4 = (idx & 127) * 4;         // col
            float4 f = *(const float4*)(X + (size_t)(row0 + r) * HH + c4);
            __half h0 = __float2half_rn(f.x);
            __half h1 = __float2half_rn(f.y);
            __half h2 = __float2half_rn(f.z);
            __half h3 = __float2half_rn(f.w);
            uint32_t hh0 = ((uint32_t)__half_as_ushort(h1) << 16) | __half_as_ushort(h0);
            uint32_t hh1 = ((uint32_t)__half_as_ushort(h3) << 16) | __half_as_ushort(h2);
            __half l0 = __float2half_rn(f.x - __half2float(h0));
            __half l1 = __float2half_rn(f.y - __half2float(h1));
            __half l2 = __float2half_rn(f.z - __half2float(h2));
            __half l3 = __float2half_rn(f.w - __half2float(h3));
            uint32_t ll0 = ((uint32_t)__half_as_ushort(l1) << 16) | __half_as_ushort(l0);
            uint32_t ll1 = ((uint32_t)__half_as_ushort(l3) << 16) | __half_as_ushort(l2);
            int off = r * ASTR_A + c4 * 2;
            *(uint2*)(ah + off) = make_uint2(hh0, hh1);
            *(uint2*)(al + off) = make_uint2(ll0, ll1);
        }
    }

    // ldmatrix lane offsets (bytes)
    const int a_off = (warp_m * 32 + (lane & 15)) * ASTR_A + ((lane >> 4) << 4);
    const int b_off = (warp_n * 32 + (lane & 7) + ((lane >> 4) << 3)) * ASTR_B
                    + (((lane >> 3) & 1) << 4);
    const uint32_t ah_base = sb + OFF_AH + a_off;
    const uint32_t al_base = sb + OFF_AL + a_off;

    float sacc[4] = {0.f, 0.f, 0.f, 0.f};   // [mi*2 + half]

    for (int nc = 0; nc < 4; nc++) {
        float acc[2][4][4];
        uint32_t corr[2][4][2];
#pragma unroll
        for (int mi = 0; mi < 2; mi++)
#pragma unroll
            for (int ni = 0; ni < 4; ni++) {
#pragma unroll
                for (int c = 0; c < 4; c++) acc[mi][ni][c] = 0.f;
                corr[mi][ni][0] = 0u; corr[mi][ni][1] = 0u;
            }

        for (int kt = 0; kt < 8; kt++) {
            const int it = nc * 8 + kt;
            const int buf = it & 1;

            CP_WAIT0();
            __syncthreads();        // B tile ready; all warps done with buf^1

            if (it < 31) {
                int nit = it + 1;
                issue_b(wh, wl, sb + OFF_B + (buf ^ 1) * BUF_SZ,
                        nit >> 3, nit & 7, tid);
            }

            const uint32_t bh_b = sb + OFF_B + buf * BUF_SZ + b_off;
            const uint32_t bl_b = bh_b + B_TILE_SZ;
            const int kbase = kt * 128;      // 64 fp16 = 128 bytes

            // A fragments: double-buffered in registers across k16 steps.
            uint32_t ah[2][2][4], al[2][2][4];   // [pipe][mi][frag]
            ldsm4(ah[0][0], ah_base + kbase);
            ldsm4(ah[0][1], ah_base + 16 * ASTR_A + kbase);
            ldsm4(al[0][0], al_base + kbase);
            ldsm4(al[0][1], al_base + 16 * ASTR_A + kbase);

#pragma unroll
            for (int k16 = 0; k16 < 4; k16++) {
                const int cur = k16 & 1;
                const int nxt = cur ^ 1;
                const int ko = k16 * 32;

                // Load B fragments for both np of this k16.
                uint32_t bh0[4], bl0[4], bh1[4], bl1[4];
                ldsm4(bh0, bh_b + ko);
                ldsm4(bl0, bl_b + ko);
                ldsm4(bh1, bh_b + 16 * ASTR_B + ko);
                ldsm4(bl1, bl_b + 16 * ASTR_B + ko);

                // Prefetch next k16's A fragments during MMAs.
                if (k16 < 3) {
                    const int ko2 = ko + 32;
                    ldsm4(ah[nxt][0], ah_base + kbase + ko2);
                    ldsm4(ah[nxt][1], ah_base + 16 * ASTR_A + kbase + ko2);
                    ldsm4(al[nxt][0], al_base + kbase + ko2);
                    ldsm4(al[nxt][1], al_base + 16 * ASTR_A + kbase + ko2);
                }

                // np = 0 (cols 0..15)
                mma_f32(acc[0][0], ah[cur][0], bh0[0], bh0[1]);
                mma_f32(acc[0][1], ah[cur][0], bh0[2], bh0[3]);
                mma_f32(acc[1][0], ah[cur][1], bh0[0], bh0[1]);
                mma_f32(acc[1][1], ah[cur][1], bh0[2], bh0[3]);
                mma_f16(corr[0][0], ah[cur][0], bl0[0], bl0[1]);
                mma_f16(corr[0][1], ah[cur][0], bl0[2], bl0[3]);
                mma_f16(corr[1][0], ah[cur][1], bl0[0], bl0[1]);
                mma_f16(corr[1][1], ah[cur][1], bl0[2], bl0[3]);
                mma_f16(corr[0][0], al[cur][0], bh0[0], bh0[1]);
                mma_f16(corr[0][1], al[cur][0], bh0[2], bh0[3]);
                mma_f16(corr[1][0], al[cur][1], bh0[0], bh0[1]);
                mma_f16(corr[1][1], al[cur][1], bh0[2], bh0[3]);
                // np = 1 (cols 16..31)
                mma_f32(acc[0][2], ah[cur][0], bh1[0], bh1[1]);
                mma_f32(acc[0][3], ah[cur][0], bh1[2], bh1[3]);
                mma_f32(acc[1][2], ah[cur][1], bh1[0], bh1[1]);
                mma_f32(acc[1][3], ah[cur][1], bh1[2], bh1[3]);
                mma_f16(corr[0][2], ah[cur][0], bl1[0], bl1[1]);
                mma_f16(corr[0][3], ah[cur][0], bl1[2], bl1[3]);
                mma_f16(corr[1][2], ah[cur][1], bl1[0], bl1[1]);
                mma_f16(corr[1][3], ah[cur][1], bl1[2], bl1[3]);
                mma_f16(corr[0][2], al[cur][0], bh1[0], bh1[1]);
                mma_f16(corr[0][3], al[cur][0], bh1[2], bh1[3]);
                mma_f16(corr[1][2], al[cur][1], bh1[0], bh1[1]);
                mma_f16(corr[1][3], al[cur][1], bh1[2], bh1[3]);
            }
        }

        // fused partial epilogue for this 128-col chunk
#pragma unroll
        for (int mi = 0; mi < 2; mi++)
#pragma unroll
            for (int ni = 0; ni < 4; ni++) {
                float2 c01 = __half22float2(*(const __half2*)&corr[mi][ni][0]);
                float2 c23 = __half22float2(*(const __half2*)&corr[mi][ni][1]);
                float cf[4] = {c01.x, c01.y, c23.x, c23.y};
#pragma unroll
                for (int c = 0; c < 4; c++) {
                    int n = nc * 128 + warp_n * 32 + ni * 8 + (lane & 3) * 2 + (c & 1);
                    float t = fast_tanh(acc[mi][ni][c] + cf[c] + sbi[n]);
                    sacc[mi * 2 + (c >> 1)] = fmaf(sv[n], t, sacc[mi * 2 + (c >> 1)]);
                }
            }
    }

    // cross-warp reduction: red[64][16]
    __syncthreads();
#pragma unroll
    for (int mi = 0; mi < 2; mi++)
#pragma unroll
        for (int half = 0; half < 2; half++) {
            int m = warp_m * 32 + mi * 16 + half * 8 + (lane >> 2);
            red[m * 16 + warp_n * 4 + (lane & 3)] = sacc[mi * 2 + half];
        }
    __syncthreads();
    if (tid < 64) {
        float s = 0.f;
#pragma unroll
        for (int j = 0; j < 16; j++) s += red[tid * 16 + j];
        scores[row0 + tid] = s;
    }
}

// ---------------------------------------------------------------------------
// Mask dtype detection: numpy bool may be serialized as int32 or uint8.
// ---------------------------------------------------------------------------
__global__ void detect_mask_kernel(const unsigned* __restrict__ mask_words)
{
    if (threadIdx.x == 0) {
        int ok = 1;
        for (int i = 0; i < 256; i++) {
            if (mask_words[i] > 1u) { ok = 0; break; }
        }
        g_mask_is_i32 = ok;
    }
}

// ---------------------------------------------------------------------------
// Masked softmax over S per batch row.
// ---------------------------------------------------------------------------
__global__ __launch_bounds__(256)
void softmax_kernel(const float* __restrict__ scores,
                    const void* __restrict__ mask,
                    float* __restrict__ attn)
{
    const int b = blockIdx.x;
    const int tid = threadIdx.x;
    __shared__ float sred[256];
    __shared__ int s_is_i32;

    if (tid == 0) s_is_i32 = g_mask_is_i32;
    __syncthreads();
    const int is_i32 = s_is_i32;

    const int* mi = (const int*)mask;
    const unsigned char* mu = (const unsigned char*)mask;

    float vals[8];
    float mx = -INFINITY;
#pragma unroll
    for (int j = 0; j < 8; j++) {
        int idx = b * SS + tid + j * 256;
        float sc = scores[idx];
        bool m = is_i32 ? (mi[idx] != 0) : (mu[idx] != 0);
        sc = m ? sc : NEGV;
        vals[j] = sc;
        mx = fmaxf(mx, sc);
    }
    sred[tid] = mx; __syncthreads();
    for (int off = 128; off > 0; off >>= 1) {
        if (tid < off) sred[tid] = fmaxf(sred[tid], sred[tid + off]);
        __syncthreads();
    }
    mx = sred[0]; __syncthreads();

    float sum = 0.f;
#pragma unroll
    for (int j = 0; j < 8; j++) {
        vals[j] = expf(vals[j] - mx);
        sum += vals[j];
    }
    sred[tid] = sum; __syncthreads();
    for (int off = 128; off > 0; off >>= 1) {
        if (tid < off) sred[tid] += sred[tid + off];
        __syncthreads();
    }
    sum = sred[0];

    float inv = 1.f / sum;
#pragma unroll
    for (int j = 0; j < 8; j++) {
        attn[b * SS + tid + j * 256] = vals[j] * inv;
    }
}

// ---------------------------------------------------------------------------
// weighted_output[b,h] = sum_s attn[b,s] * X[b,s,h]
// Stage 1: S split 8 ways -> partials (grid 64x4x8). Stage 2: reduce.
// ---------------------------------------------------------------------------
__global__ __launch_bounds__(128)
void weighted_part_kernel(const float* __restrict__ X,
                          const float* __restrict__ attn,
                          float* __restrict__ part)
{
    const int b  = blockIdx.x;
    const int h  = blockIdx.y * 128 + threadIdx.x;
    const int sc = blockIdx.z;              // 0..7, 256 s each
    const int s0 = sc * 256;
    const float* xb = X + (size_t)b * SS * HH + (size_t)s0 * HH + h;
    const float* ab = attn + b * SS + s0;

    float a0 = 0.f, a1 = 0.f, a2 = 0.f, a3 = 0.f;
#pragma unroll 4
    for (int s = 0; s < 256; s += 4) {
        a0 = fmaf(__ldg(&ab[s + 0]), __ldg(&xb[(size_t)(s + 0) * HH]), a0);
        a1 = fmaf(__ldg(&ab[s + 1]), __ldg(&xb[(size_t)(s + 1) * HH]), a1);
        a2 = fmaf(__ldg(&ab[s + 2]), __ldg(&xb[(size_t)(s + 2) * HH]), a2);
        a3 = fmaf(__ldg(&ab[s + 3]), __ldg(&xb[(size_t)(s + 3) * HH]), a3);
    }
    part[((size_t)sc * BB + b) * HH + h] = (a0 + a1) + (a2 + a3);
}

__global__ __launch_bounds__(256)
void weighted_reduce_kernel(const float* __restrict__ part,
                            float* __restrict__ out)
{
    int idx = blockIdx.x * 256 + threadIdx.x;   // BB*HH = 32768
    float s = 0.f;
#pragma unroll
    for (int j = 0; j < 8; j++) s += part[j * BB * HH + idx];
    out[idx] = s;
}

// ---------------------------------------------------------------------------
extern "C" void kernel_launch(void* const* d_in, const int* in_sizes, int n_in,
                              void* d_out, int out_size)
{
    const float* X    = (const float*)d_in[0];   // [B,S,H]
    const void*  mask = d_in[1];                 // [B,S] bool (int32 or uint8)
    const float* W    = (const float*)d_in[2];   // [H,H]
    const float* bias = (const float*)d_in[3];   // [H]
    const float* v    = (const float*)d_in[4];   // [H]
    float* out = (float*)d_out;

    // Output layout: weighted_output [B,H] first, attn_weights [B,S] second.
    float* attn;
    if (out_size >= BB * HH + TOK) {
        attn = out + BB * HH;
    } else {
        void* p = nullptr;
        cudaGetSymbolAddress(&p, g_attn_fallback);
        attn = (float*)p;
    }
    void* sp = nullptr; cudaGetSymbolAddress(&sp, g_scores);
    float* scores = (float*)sp;
    void* pp = nullptr; cudaGetSymbolAddress(&pp, g_part);
    float* part = (float*)pp;
    void* whp = nullptr; cudaGetSymbolAddress(&whp, g_wh);
    void* wlp = nullptr; cudaGetSymbolAddress(&wlp, g_wl);
    __half* wh = (__half*)whp;
    __half* wl = (__half*)wlp;

    cudaFuncSetAttribute(scores_tc_kernel,
                         cudaFuncAttributeMaxDynamicSharedMemorySize, SMEM_TOTAL);

    detect_mask_kernel<<<1, 32>>>((const unsigned*)mask);   // idx 0
    wsplit_kernel<<<HH * HH / 1024, 256>>>(W, wh, wl);      // idx 1
    dummy_kernel<<<1, 32>>>();                              // idx 2 (ncu slot shim)
    scores_tc_kernel<<<TOK / 64, NTHR, SMEM_TOTAL>>>(X, wh, wl, bias, v, scores); // idx 3
    softmax_kernel<<<BB, 256>>>(scores, mask, attn);
    weighted_part_kernel<<<dim3(BB, HH / 128, 8), 128>>>(X, attn, part);
    weighted_reduce_kernel<<<BB * HH / 256, 256>>>(part, out);
}